// round 6
// baseline (speedup 1.0000x reference)
#include <cuda_runtime.h>
#include <math.h>

#define B_SZ   2048
#define T_SZ   512
#define D_IN   64
#define H_SZ   128
#define D_OUT  64
#define M_TILE 16
#define NTHREADS 128
#define NSTEPS (T_SZ - 1)

// SMEM layout (floats):
//  [0      .. 16384)  Whh_t  (k-major: Whh_t[k*H+j] = W_hh[j*H+k])
//  [16384  .. 32768)  W1t    (reused post-loop for W_out_t)
//  [32768  .. 49152)  Pt     (k-major P^T view: Pt[k*H+j] = P[j][k], P = W1@W2)
//  [49152  .. 51200)  buf0   [16][128]
//  [51200  .. 53248)  buf1   [16][128]
//  [53248  .. 53376)  v_s
//  [53376  .. 53504)  c_s
//  [53504  .. 53632)  b1_s
//  [53632  .. 53760)  b2_s
//  [53760  .. 53888)  c1_s   (b2 @ W1^T)
//  [53888  .. 53904)  xs
#define OFF_WHH 0
#define OFF_W1  16384
#define OFF_P   32768
#define OFF_B0  49152
#define OFF_B1  51200
#define OFF_V   53248
#define OFF_C   53376
#define OFF_BB1 53504
#define OFF_BB2 53632
#define OFF_C1  53760
#define OFF_XS  53888
#define SMEM_FLOATS 53904
#define SMEM_BYTES  (SMEM_FLOATS * 4)   // 215616 B

// Precomputed by prep_kernel:
__device__ float g_P[H_SZ * H_SZ];    // g_P[k*H+j]   = sum_m W1[j][m] * W2[m][k]
__device__ float g_W2t[H_SZ * H_SZ];  // g_W2t[k*H+j] = W2[j][k]

__global__ void prep_kernel(const float* __restrict__ W1,
                            const float* __restrict__ W2) {
    __shared__ float w1row[H_SZ];
    const int j = blockIdx.x;
    const int k = threadIdx.x;
    w1row[k] = W1[j * H_SZ + k];
    __syncthreads();
    float s = 0.0f;
#pragma unroll 8
    for (int m = 0; m < H_SZ; m++)
        s = fmaf(w1row[m], W2[m * H_SZ + k], s);
    g_P[k * H_SZ + j]   = s;
    g_W2t[k * H_SZ + j] = W2[j * H_SZ + k];
}

__device__ __forceinline__ void gemm_acc(const float* __restrict__ Wt,
                                         const float* __restrict__ bufp,
                                         int rbase, int j0, float acc[4][4]) {
#pragma unroll 8
    for (int k = 0; k < H_SZ; k += 4) {
        const float4 w0 = *reinterpret_cast<const float4*>(Wt + (k + 0) * H_SZ + j0);
        const float4 w1 = *reinterpret_cast<const float4*>(Wt + (k + 1) * H_SZ + j0);
        const float4 w2 = *reinterpret_cast<const float4*>(Wt + (k + 2) * H_SZ + j0);
        const float4 w3 = *reinterpret_cast<const float4*>(Wt + (k + 3) * H_SZ + j0);
#pragma unroll
        for (int ri = 0; ri < 4; ri++) {
            const float4 a = *reinterpret_cast<const float4*>(bufp + (rbase + ri) * H_SZ + k);
            acc[ri][0] = fmaf(a.x, w0.x, acc[ri][0]);
            acc[ri][1] = fmaf(a.x, w0.y, acc[ri][1]);
            acc[ri][2] = fmaf(a.x, w0.z, acc[ri][2]);
            acc[ri][3] = fmaf(a.x, w0.w, acc[ri][3]);
            acc[ri][0] = fmaf(a.y, w1.x, acc[ri][0]);
            acc[ri][1] = fmaf(a.y, w1.y, acc[ri][1]);
            acc[ri][2] = fmaf(a.y, w1.z, acc[ri][2]);
            acc[ri][3] = fmaf(a.y, w1.w, acc[ri][3]);
            acc[ri][0] = fmaf(a.z, w2.x, acc[ri][0]);
            acc[ri][1] = fmaf(a.z, w2.y, acc[ri][1]);
            acc[ri][2] = fmaf(a.z, w2.z, acc[ri][2]);
            acc[ri][3] = fmaf(a.z, w2.w, acc[ri][3]);
            acc[ri][0] = fmaf(a.w, w3.x, acc[ri][0]);
            acc[ri][1] = fmaf(a.w, w3.y, acc[ri][1]);
            acc[ri][2] = fmaf(a.w, w3.z, acc[ri][2]);
            acc[ri][3] = fmaf(a.w, w3.w, acc[ri][3]);
        }
    }
}

// Same, but weights streamed from global (L2-resident).
__device__ __forceinline__ void gemm_acc_glb(const float* __restrict__ Wt,
                                             const float* __restrict__ bufp,
                                             int rbase, int j0, float acc[4][4]) {
#pragma unroll 8
    for (int k = 0; k < H_SZ; k += 4) {
        const float4 w0 = __ldg(reinterpret_cast<const float4*>(Wt + (k + 0) * H_SZ + j0));
        const float4 w1 = __ldg(reinterpret_cast<const float4*>(Wt + (k + 1) * H_SZ + j0));
        const float4 w2 = __ldg(reinterpret_cast<const float4*>(Wt + (k + 2) * H_SZ + j0));
        const float4 w3 = __ldg(reinterpret_cast<const float4*>(Wt + (k + 3) * H_SZ + j0));
#pragma unroll
        for (int ri = 0; ri < 4; ri++) {
            const float4 a = *reinterpret_cast<const float4*>(bufp + (rbase + ri) * H_SZ + k);
            acc[ri][0] = fmaf(a.x, w0.x, acc[ri][0]);
            acc[ri][1] = fmaf(a.x, w0.y, acc[ri][1]);
            acc[ri][2] = fmaf(a.x, w0.z, acc[ri][2]);
            acc[ri][3] = fmaf(a.x, w0.w, acc[ri][3]);
            acc[ri][0] = fmaf(a.y, w1.x, acc[ri][0]);
            acc[ri][1] = fmaf(a.y, w1.y, acc[ri][1]);
            acc[ri][2] = fmaf(a.y, w1.z, acc[ri][2]);
            acc[ri][3] = fmaf(a.y, w1.w, acc[ri][3]);
            acc[ri][0] = fmaf(a.z, w2.x, acc[ri][0]);
            acc[ri][1] = fmaf(a.z, w2.y, acc[ri][1]);
            acc[ri][2] = fmaf(a.z, w2.z, acc[ri][2]);
            acc[ri][3] = fmaf(a.z, w2.w, acc[ri][3]);
            acc[ri][0] = fmaf(a.w, w3.x, acc[ri][0]);
            acc[ri][1] = fmaf(a.w, w3.y, acc[ri][1]);
            acc[ri][2] = fmaf(a.w, w3.z, acc[ri][2]);
            acc[ri][3] = fmaf(a.w, w3.w, acc[ri][3]);
        }
    }
}

__device__ __forceinline__ void stage4(float* __restrict__ bufp, int rbase, int j0,
                                       const float v[4][4]) {
#pragma unroll
    for (int ri = 0; ri < 4; ri++) {
        *reinterpret_cast<float4*>(bufp + (rbase + ri) * H_SZ + j0) =
            make_float4(v[ri][0], v[ri][1], v[ri][2], v[ri][3]);
    }
}

__device__ __forceinline__ float silu_f(float v) {
    return v / (1.0f + __expf(-v));
}

__global__ void __launch_bounds__(NTHREADS, 1)
rnnode_kernel(const float* __restrict__ x, const float* __restrict__ span,
              const float* __restrict__ W_emb, const float* __restrict__ b_emb,
              const float* __restrict__ W_ih, const float* __restrict__ b_ih,
              const float* __restrict__ W_hh, const float* __restrict__ b_hh,
              const float* __restrict__ W1, const float* __restrict__ b1,
              const float* __restrict__ W2, const float* __restrict__ b2,
              const float* __restrict__ W_out, const float* __restrict__ b_out,
              float* __restrict__ out) {
    extern __shared__ float sm[];
    float* Whh_t = sm + OFF_WHH;
    float* W1t   = sm + OFF_W1;
    float* Pt    = sm + OFF_P;
    float* buf0  = sm + OFF_B0;
    float* buf1  = sm + OFF_B1;
    float* v_s   = sm + OFF_V;
    float* c_s   = sm + OFF_C;
    float* b1_s  = sm + OFF_BB1;
    float* b2_s  = sm + OFF_BB2;
    float* c1_s  = sm + OFF_C1;
    float* xs    = sm + OFF_XS;

    const int tid = threadIdx.x;
    const int b0  = blockIdx.x * M_TILE;

    // Load weights transposed to k-major; P already k-major in global.
    for (int i = tid; i < H_SZ * H_SZ; i += NTHREADS) {
        const int j = i >> 7, k = i & 127;
        Whh_t[k * H_SZ + j] = W_hh[i];
        W1t[k * H_SZ + j]   = W1[i];
        Pt[i] = g_P[i];
    }
    // Fold input path + aux vectors.
    if (tid < H_SZ) {
        float vv = 0.0f, cc = 0.0f;
        for (int d = 0; d < D_IN; d++) {
            const float w = W_ih[tid * D_IN + d];
            vv = fmaf(w, W_emb[d], vv);
            cc = fmaf(w, b_emb[d], cc);
        }
        v_s[tid]  = vv;
        c_s[tid]  = cc + b_ih[tid] + b_hh[tid];
        b1_s[tid] = b1[tid];
        b2_s[tid] = b2[tid];
        // c1 = b2 @ W1^T : c1[j] = sum_k b2[k] * W1[j][k]
        float c1v = 0.0f;
        for (int k = 0; k < H_SZ; k++)
            c1v = fmaf(b2[k], W1[tid * H_SZ + k], c1v);
        c1_s[tid] = c1v;
    }
    __syncthreads();

    const int rg    = tid >> 5;
    const int lane  = tid & 31;
    const int rbase = rg * 4;
    const int j0    = lane * 4;

    const float4 b1v = *reinterpret_cast<const float4*>(b1_s + j0);
    const float4 b2v = *reinterpret_cast<const float4*>(b2_s + j0);
    const float4 c1v = *reinterpret_cast<const float4*>(c1_s + j0);
    const float4 vv  = *reinterpret_cast<const float4*>(v_s + j0);
    const float4 cc  = *reinterpret_cast<const float4*>(c_s + j0);
    const float b1a[4] = {b1v.x, b1v.y, b1v.z, b1v.w};
    const float b2a[4] = {b2v.x, b2v.y, b2v.z, b2v.w};
    const float c1a[4] = {c1v.x, c1v.y, c1v.z, c1v.w};

    float h[4][4];
#pragma unroll
    for (int ri = 0; ri < 4; ri++)
#pragma unroll
        for (int c = 0; c < 4; c++) h[ri][c] = 0.0f;

    int p = 0;
#define BUF(pp) ((pp) ? buf1 : buf0)

    for (int t = 0; t < NSTEPS; t++) {
        const float dt   = __ldg(span + t + 1) - __ldg(span + t);
        const float dt3  = dt * (1.0f / 3.0f);
        const float dt23 = dt3 * 2.0f;
        const float dt8  = dt * 0.125f;

        float acc[4][4];
        float z1[4][4], u1[4][4], u2[4][4], u3[4][4];

        // ---- G1: h = tanh(x*v + c + h @ Whh^T) ----
        stage4(BUF(p), rbase, j0, h);
        if (tid < M_TILE) xs[tid] = x[(size_t)(b0 + tid) * T_SZ + t];
        __syncthreads();
#pragma unroll
        for (int ri = 0; ri < 4; ri++) {
            const float xv = xs[rbase + ri];
            acc[ri][0] = fmaf(xv, vv.x, cc.x);
            acc[ri][1] = fmaf(xv, vv.y, cc.y);
            acc[ri][2] = fmaf(xv, vv.z, cc.z);
            acc[ri][3] = fmaf(xv, vv.w, cc.w);
        }
        gemm_acc(Whh_t, BUF(p), rbase, j0, acc);
        p ^= 1;
#pragma unroll
        for (int ri = 0; ri < 4; ri++)
#pragma unroll
            for (int c = 0; c < 4; c++) h[ri][c] = tanhf(acc[ri][c]);

        // ---- G2: z1 = h @ W1^T + b1 ; u1 = silu(z1) ----
        stage4(BUF(p), rbase, j0, h);
        __syncthreads();
#pragma unroll
        for (int ri = 0; ri < 4; ri++)
#pragma unroll
            for (int c = 0; c < 4; c++) acc[ri][c] = b1a[c];
        gemm_acc(W1t, BUF(p), rbase, j0, acc);
        p ^= 1;
#pragma unroll
        for (int ri = 0; ri < 4; ri++)
#pragma unroll
            for (int c = 0; c < 4; c++) {
                z1[ri][c] = acc[ri][c];
                u1[ri][c] = silu_f(acc[ri][c]);
            }

        // ---- G3: z2 = z1 + dt/3*(u1 @ P^T + c1) ; u2 = silu(z2) ----
        stage4(BUF(p), rbase, j0, u1);
        __syncthreads();
#pragma unroll
        for (int ri = 0; ri < 4; ri++)
#pragma unroll
            for (int c = 0; c < 4; c++) acc[ri][c] = c1a[c];
        gemm_acc(Pt, BUF(p), rbase, j0, acc);
        p ^= 1;
#pragma unroll
        for (int ri = 0; ri < 4; ri++)
#pragma unroll
            for (int c = 0; c < 4; c++)
                u2[ri][c] = silu_f(fmaf(dt3, acc[ri][c], z1[ri][c]));

        // ---- G4: z3 = z1 + dt*((u2 - u1/3) @ P^T) + (2dt/3)*c1 ; u3 ----
        {
            float g2[4][4];
#pragma unroll
            for (int ri = 0; ri < 4; ri++)
#pragma unroll
                for (int c = 0; c < 4; c++)
                    g2[ri][c] = fmaf(-(1.0f / 3.0f), u1[ri][c], u2[ri][c]);
            stage4(BUF(p), rbase, j0, g2);
        }
        __syncthreads();
#pragma unroll
        for (int ri = 0; ri < 4; ri++)
#pragma unroll
            for (int c = 0; c < 4; c++) acc[ri][c] = 0.0f;
        gemm_acc(Pt, BUF(p), rbase, j0, acc);
        p ^= 1;
#pragma unroll
        for (int ri = 0; ri < 4; ri++)
#pragma unroll
            for (int c = 0; c < 4; c++)
                u3[ri][c] = silu_f(fmaf(dt, acc[ri][c],
                                        fmaf(dt23, c1a[c], z1[ri][c])));

        // ---- G5: z4 = z1 + dt*((u1 - u2 + u3) @ P^T + c1) ; u4 -> g4 ----
        {
            float g3[4][4];
#pragma unroll
            for (int ri = 0; ri < 4; ri++)
#pragma unroll
                for (int c = 0; c < 4; c++)
                    g3[ri][c] = u1[ri][c] - u2[ri][c] + u3[ri][c];
            stage4(BUF(p), rbase, j0, g3);
        }
        __syncthreads();
#pragma unroll
        for (int ri = 0; ri < 4; ri++)
#pragma unroll
            for (int c = 0; c < 4; c++) acc[ri][c] = c1a[c];
        gemm_acc(Pt, BUF(p), rbase, j0, acc);
        p ^= 1;

        // ---- G6: h += (dt/8)*(g4 @ W2^T) + dt*b2, g4 = u1+3(u2+u3)+u4 ----
        {
            float g4[4][4];
#pragma unroll
            for (int ri = 0; ri < 4; ri++)
#pragma unroll
                for (int c = 0; c < 4; c++) {
                    const float z4 = fmaf(dt, acc[ri][c], z1[ri][c]);
                    const float u4 = silu_f(z4);
                    g4[ri][c] = fmaf(3.0f, u2[ri][c] + u3[ri][c],
                                     u1[ri][c] + u4);
                }
            stage4(BUF(p), rbase, j0, g4);
        }
        __syncthreads();
#pragma unroll
        for (int ri = 0; ri < 4; ri++)
#pragma unroll
            for (int c = 0; c < 4; c++) acc[ri][c] = 0.0f;
        gemm_acc_glb(g_W2t, BUF(p), rbase, j0, acc);
        p ^= 1;
#pragma unroll
        for (int ri = 0; ri < 4; ri++)
#pragma unroll
            for (int c = 0; c < 4; c++)
                h[ri][c] = fmaf(dt8, acc[ri][c],
                                fmaf(dt, b2a[c], h[ri][c]));
    }

    // ---- out = h @ W_out^T + b_out ----
    __syncthreads();
    for (int i = tid; i < D_OUT * H_SZ; i += NTHREADS) {
        const int j = i >> 7, k = i & 127;
        W1t[k * D_OUT + j] = W_out[i];
    }
    float* bp = BUF(p);
    stage4(bp, rbase, j0, h);
    __syncthreads();

    const int jo = lane * 2;
#pragma unroll
    for (int ri = 0; ri < 4; ri++) {
        float o0 = __ldg(b_out + jo);
        float o1 = __ldg(b_out + jo + 1);
        const float* br = bp + (rbase + ri) * H_SZ;
#pragma unroll 16
        for (int k = 0; k < H_SZ; k++) {
            const float a = br[k];
            const float2 w = *reinterpret_cast<const float2*>(W1t + k * D_OUT + jo);
            o0 = fmaf(a, w.x, o0);
            o1 = fmaf(a, w.y, o1);
        }
        *reinterpret_cast<float2*>(out + (size_t)(b0 + rbase + ri) * D_OUT + jo) =
            make_float2(o0, o1);
    }
}

extern "C" void kernel_launch(void* const* d_in, const int* in_sizes, int n_in,
                              void* d_out, int out_size) {
    const float* x     = (const float*)d_in[0];
    const float* span  = (const float*)d_in[1];
    const float* W_emb = (const float*)d_in[2];
    const float* b_emb = (const float*)d_in[3];
    const float* W_ih  = (const float*)d_in[4];
    const float* b_ih  = (const float*)d_in[5];
    const float* W_hh  = (const float*)d_in[6];
    const float* b_hh  = (const float*)d_in[7];
    const float* W1    = (const float*)d_in[8];
    const float* b1    = (const float*)d_in[9];
    const float* W2    = (const float*)d_in[10];
    const float* b2    = (const float*)d_in[11];
    const float* W_out = (const float*)d_in[12];
    const float* b_out = (const float*)d_in[13];
    float* out = (float*)d_out;

    prep_kernel<<<H_SZ, H_SZ>>>(W1, W2);
    cudaFuncSetAttribute(rnnode_kernel,
                         cudaFuncAttributeMaxDynamicSharedMemorySize, SMEM_BYTES);
    rnnode_kernel<<<B_SZ / M_TILE, NTHREADS, SMEM_BYTES>>>(
        x, span, W_emb, b_emb, W_ih, b_ih, W_hh, b_hh,
        W1, b1, W2, b2, W_out, b_out, out);
}